// round 16
// baseline (speedup 1.0000x reference)
#include <cuda_runtime.h>

#define NMAX 5000000

// Scratch (__device__ globals only — no allocation allowed)
// g_deg storage is used as int counters during k_deg, then overwritten with
// dis = rsqrt(deg) (float) in k_prep.
__device__ float g_deg[NMAX];   // phase 1: int edge-count (aliased); phase 2: dis
__device__ float g_xwd[NMAX];   // x*w*rsqrt(deg)
__device__ float g_s[NMAX];     // sum over incoming edges of xwd[src]
__device__ int   g_is64;        // 1 if edge_index is int64 on device

// ---------------------------------------------------------------------------
// K0: zero int counters (vectorized). Thread 0 of block 0 probes dtype.
__global__ void k_init(const unsigned int* __restrict__ e, int n) {
    int i = blockIdx.x * blockDim.x + threadIdx.x;
    int n4 = n >> 2;
    if (i < n4) {
        ((int4*)g_deg)[i] = make_int4(0, 0, 0, 0);
    }
    // tail
    int t = 4 * n4 + i;
    if (i < (n - 4 * n4)) ((int*)g_deg)[t] = 0;
    if (blockIdx.x == 0 && threadIdx.x == 0) {
        int is64 = 1;
        #pragma unroll 1
        for (int k = 0; k < 64; k++) {
            unsigned lo = e[2 * k];
            unsigned hi = e[2 * k + 1];
            if (hi != 0u || lo >= (unsigned)n) { is64 = 0; break; }
        }
        g_is64 = is64;
    }
}

// K1: degree count over edge targets — INTEGER atomics (exact, simplest LTS op).
__global__ void k_deg(const void* __restrict__ ei, long long ne) {
    int is64 = g_is64;
    int* cnt = (int*)g_deg;
    long long q = ne >> 3;                       // number of 8-edge groups
    long long stride = (long long)gridDim.x * blockDim.x;
    long long t0 = (long long)blockIdx.x * blockDim.x + threadIdx.x;

    if (is64) {
        const longlong2* col2 = (const longlong2*)((const long long*)ei + ne);
        for (long long g = t0; g < q; g += stride) {
            longlong2 a = col2[4 * g];
            longlong2 b = col2[4 * g + 1];
            longlong2 c = col2[4 * g + 2];
            longlong2 d = col2[4 * g + 3];
            atomicAdd(&cnt[(int)a.x], 1);
            atomicAdd(&cnt[(int)a.y], 1);
            atomicAdd(&cnt[(int)b.x], 1);
            atomicAdd(&cnt[(int)b.y], 1);
            atomicAdd(&cnt[(int)c.x], 1);
            atomicAdd(&cnt[(int)c.y], 1);
            atomicAdd(&cnt[(int)d.x], 1);
            atomicAdd(&cnt[(int)d.y], 1);
        }
        const long long* col = (const long long*)ei + ne;
        for (long long i = 8 * q + t0; i < ne; i += stride)
            atomicAdd(&cnt[(int)col[i]], 1);
    } else {
        const int4* col4 = (const int4*)((const int*)ei + ne);
        for (long long g = t0; g < q; g += stride) {
            int4 c0 = col4[2 * g];
            int4 c1 = col4[2 * g + 1];
            atomicAdd(&cnt[c0.x], 1);
            atomicAdd(&cnt[c0.y], 1);
            atomicAdd(&cnt[c0.z], 1);
            atomicAdd(&cnt[c0.w], 1);
            atomicAdd(&cnt[c1.x], 1);
            atomicAdd(&cnt[c1.y], 1);
            atomicAdd(&cnt[c1.z], 1);
            atomicAdd(&cnt[c1.w], 1);
        }
        const int* col = (const int*)ei + ne;
        for (long long i = 8 * q + t0; i < ne; i += stride)
            atomicAdd(&cnt[col[i]], 1);
    }
}

// K2: dis = rsqrt(cnt+1) (self loop folded in); xwd = x*w*dis; zero g_s.
__global__ void k_prep(const float* __restrict__ x, const float* __restrict__ conv_w, int n) {
    int i = blockIdx.x * blockDim.x + threadIdx.x;
    if (i < n) {
        int cnt = ((const int*)g_deg)[i];
        float dis = rsqrtf((float)(cnt + 1));
        g_deg[i] = dis;                       // store dis for k_final
        g_xwd[i] = x[i] * conv_w[0] * dis;
        g_s[i]   = 0.0f;
    }
}

// K3: s[col] += xwd[row]. 4 edges/thread/iter (measured at 94% LTS; do not touch).
__global__ void k_scatter(const void* __restrict__ ei, long long ne) {
    int is64 = g_is64;
    long long q = ne >> 2;
    long long stride = (long long)gridDim.x * blockDim.x;
    long long t0 = (long long)blockIdx.x * blockDim.x + threadIdx.x;

    if (is64) {
        const longlong2* row2 = (const longlong2*)((const long long*)ei);
        const longlong2* col2 = (const longlong2*)((const long long*)ei + ne);
        for (long long g = t0; g < q; g += stride) {
            longlong2 ra = row2[2 * g], rb = row2[2 * g + 1];
            longlong2 ca = col2[2 * g], cb = col2[2 * g + 1];
            float v0 = g_xwd[(int)ra.x];
            float v1 = g_xwd[(int)ra.y];
            float v2 = g_xwd[(int)rb.x];
            float v3 = g_xwd[(int)rb.y];
            atomicAdd(&g_s[(int)ca.x], v0);
            atomicAdd(&g_s[(int)ca.y], v1);
            atomicAdd(&g_s[(int)cb.x], v2);
            atomicAdd(&g_s[(int)cb.y], v3);
        }
        const long long* row = (const long long*)ei;
        const long long* col = (const long long*)ei + ne;
        for (long long i = 4 * q + t0; i < ne; i += stride)
            atomicAdd(&g_s[(int)col[i]], g_xwd[(int)row[i]]);
    } else {
        const int4* row4 = (const int4*)((const int*)ei);
        const int4* col4 = (const int4*)((const int*)ei + ne);
        for (long long g = t0; g < q; g += stride) {
            int4 r = row4[g];
            int4 c = col4[g];
            float v0 = g_xwd[r.x];
            float v1 = g_xwd[r.y];
            float v2 = g_xwd[r.z];
            float v3 = g_xwd[r.w];
            atomicAdd(&g_s[c.x], v0);
            atomicAdd(&g_s[c.y], v1);
            atomicAdd(&g_s[c.z], v2);
            atomicAdd(&g_s[c.w], v3);
        }
        const int* row = (const int*)ei;
        const int* col = (const int*)ei + ne;
        for (long long i = 4 * q + t0; i < ne; i += stride)
            atomicAdd(&g_s[col[i]], g_xwd[row[i]]);
    }
}

// K4: per-graph FC readout. One warp per graph (50 nodes). g_deg holds dis.
__global__ void k_final(const float* __restrict__ conv_b,
                        const float* __restrict__ fc_w,
                        const float* __restrict__ fc_b,
                        float* __restrict__ out, int ngraphs) {
    int gwarp = (blockIdx.x * blockDim.x + threadIdx.x) >> 5;
    int lane = threadIdx.x & 31;
    if (gwarp >= ngraphs) return;
    float b = conv_b[0];
    float p0 = 0.0f, p1 = 0.0f;
    int base = gwarp * 50;
    for (int j = lane; j < 50; j += 32) {
        int idx = base + j;
        float h = g_deg[idx] * (g_s[idx] + g_xwd[idx]) + b;
        p0 = fmaf(h, fc_w[j],      p0);
        p1 = fmaf(h, fc_w[50 + j], p1);
    }
    #pragma unroll
    for (int off = 16; off; off >>= 1) {
        p0 += __shfl_xor_sync(0xffffffffu, p0, off);
        p1 += __shfl_xor_sync(0xffffffffu, p1, off);
    }
    if (lane == 0) {
        out[gwarp * 2 + 0] = p0 + fc_b[0];
        out[gwarp * 2 + 1] = p1 + fc_b[1];
    }
}

// ---------------------------------------------------------------------------
extern "C" void kernel_launch(void* const* d_in, const int* in_sizes, int n_in,
                              void* d_out, int out_size) {
    const float* x      = (const float*)d_in[0];   // [N,1] f32
    const void*  ei     = d_in[1];                 // [2,E] int32 or int64
    const float* conv_w = (const float*)d_in[2];   // [1,1]
    const float* conv_b = (const float*)d_in[3];   // [1]
    const float* fc_w   = (const float*)d_in[4];   // [2,50]
    const float* fc_b   = (const float*)d_in[5];   // [2]
    float*       out    = (float*)d_out;           // [G,2]

    int       n  = in_sizes[0];                    // 5,000,000 nodes
    long long ne = (long long)in_sizes[1] / 2;     // 80,000,000 edges
    int       ng = out_size / 2;                   // 100,000 graphs

    const int T = 256;
    int edge_blocks = 148 * 16;   // 2368 blocks (measured-best)

    // 5 launches; k_scatter stays in the ncu capture slot (position 4).
    k_init<<<(n / 4 + T - 1) / T, T>>>((const unsigned int*)ei, n);
    k_deg<<<edge_blocks, T>>>(ei, ne);
    k_prep<<<(n + T - 1) / T, T>>>(x, conv_w, n);
    k_scatter<<<edge_blocks, T>>>(ei, ne);

    long long fin_threads = (long long)ng * 32;
    k_final<<<(unsigned)((fin_threads + T - 1) / T), T>>>(conv_b, fc_w, fc_b, out, ng);
}